// round 7
// baseline (speedup 1.0000x reference)
#include <cuda_runtime.h>
#include <math_constants.h>

#define B_ 1024
#define D_ 512
#define O_ 256
#define NSPLIT 8

// ---- scratch (no allocations allowed) ----
__device__ float  g_Mpart[NSPLIT * D_ * O_];
__device__ float  g_relx[D_ * O_];
__device__ float  g_relwT[O_ * B_];          // rel_w transposed [o][b]
__device__ float  g_Sx[D_];
__device__ float  g_pmT[O_ * D_];            // prefix-min of w, transposed [o][d]
__device__ int    g_argw[O_];
__device__ float  g_xT[D_ * B_];             // x transposed [d][b]
__device__ float  g_tT[O_ * B_];             // t transposed [o][b]
__device__ float  g_wval[O_ * D_];           // bucket-ordered a'=1-w per o
__device__ int    g_wbs[O_ * 260];           // bucket starts per o
__device__ double g_wbp[O_ * 256];           // fp64 inclusive prefix of bucket sums

// ============================================================
// kA: [0,256) k1 partials (64x64 tile, 4x4/thread)
//     [256,768) Sx | [768,1024) w-prep | [1024,1536) transpose x
//     [1536,1792) transpose t
// ============================================================
__global__ __launch_bounds__(256) void kA(const float* __restrict__ x,
                                          const float* __restrict__ w,
                                          const float* __restrict__ tt) {
    __shared__ __align__(16) unsigned char raw[16384];
    __shared__ int s_argw;
    const int blk = blockIdx.x;
    const int t = threadIdx.x;

    if (blk < 256) {
        // ---- k1 partials: per-cell b-order IDENTICAL to R2 k1 ----
        float (*xs)[64] = (float(*)[64])raw;          // [bb][dd] 8KB
        float (*ts)[64] = (float(*)[64])(raw + 8192); // [bb][oo] 8KB
        const int d0 = (blk & 7) * 64;
        const int o0 = ((blk >> 3) & 3) * 64;
        const int bz = blk >> 5;
        const int b0 = bz * (B_ / NSPLIT);
        const int dg = t & 15;        // 16 d-groups x 4
        const int og = t >> 4;        // 16 o-groups x 4
        float acc[4][4];
#pragma unroll
        for (int i = 0; i < 4; i++)
#pragma unroll
            for (int j = 0; j < 4; j++) acc[i][j] = 0.0f;
        for (int bc = 0; bc < B_ / NSPLIT; bc += 32) {
#pragma unroll
            for (int i = t; i < 32 * 64; i += 256) {
                int bb = i >> 6, dd = i & 63;
                xs[bb][dd] = 1.0f - x[(b0 + bc + bb) * D_ + d0 + dd];
            }
#pragma unroll
            for (int i = t; i < 32 * 64; i += 256) {
                int bb = i >> 6, oo = i & 63;
                ts[bb][oo] = 1.0f - tt[(b0 + bc + bb) * O_ + o0 + oo];
            }
            __syncthreads();
#pragma unroll 4
            for (int bb = 0; bb < 32; ++bb) {
                float xv[4], tv[4];
#pragma unroll
                for (int i = 0; i < 4; i++) xv[i] = xs[bb][dg * 4 + i];
#pragma unroll
                for (int j = 0; j < 4; j++) tv[j] = ts[bb][og * 4 + j];
#pragma unroll
                for (int i = 0; i < 4; i++)
#pragma unroll
                    for (int j = 0; j < 4; j++)
                        acc[i][j] += fminf(xv[i], tv[j]);
            }
            __syncthreads();
        }
        float* outp = g_Mpart + bz * (D_ * O_);
#pragma unroll
        for (int i = 0; i < 4; i++)
#pragma unroll
            for (int j = 0; j < 4; j++)
                outp[(d0 + dg * 4 + i) * O_ + (o0 + og * 4 + j)] = acc[i][j];
    } else if (blk < 768) {
        // ---- Sx[d] (identical math) ----
        float* sm = (float*)raw;
        int d = blk - 256;
        float s = 0.0f;
        for (int b = t; b < B_; b += 256) s += (1.0f - x[b * D_ + d]);
        sm[t] = s; __syncthreads();
        for (int k = 128; k > 0; k >>= 1) {
            if (t < k) sm[t] += sm[t + k];
            __syncthreads();
        }
        if (t == 0) g_Sx[d] = sm[0];
    } else if (blk < 1024) {
        // ---- per-o: prefix-min -> pmT, argw, bucket (1-w), fp64 prefix ----
        const int o = blk - 768;
        float*  F0 = (float*)raw;
        float*  F1 = (float*)(raw + 2048);
        float*  F2 = (float*)(raw + 4096);
        int*    KY = (int*)(raw + 6144);
        int*    H0 = (int*)(raw + 8192);
        int*    H1 = (int*)(raw + 9216);
        double* P0 = (double*)(raw + 10240);
        double* P1 = (double*)(raw + 12288);

        F0[t] = w[t * O_ + o];
        F0[t + 256] = w[(t + 256) * O_ + o];
        if (t == 0) s_argw = 0x7FFFFFFF;
        F1[t] = F0[t]; F1[t + 256] = F0[t + 256];
        {
            float* src = F1; float* dst = F2;
            for (int off = 1; off < D_; off <<= 1) {
                __syncthreads();
                for (int e = t; e < D_; e += 256) {
                    float v = src[e];
                    if (e >= off) v = fminf(v, src[e - off]);
                    dst[e] = v;
                }
                float* tmp = src; src = dst; dst = tmp;
            }
            __syncthreads();
            for (int e = t; e < D_; e += 256) g_pmT[o * D_ + e] = src[e];
            float wmin = src[D_ - 1];
            __syncthreads();
            for (int e = t; e < D_; e += 256)
                if (F0[e] == wmin) atomicMin(&s_argw, e);
        }
        H0[t] = 0;
        __syncthreads();
        for (int e = t; e < D_; e += 256) {
            float a = 1.0f - F0[e];
            int k = (int)(a * 256.0f); k = max(0, min(255, k));
            KY[e] = k;
            atomicAdd(&H0[k], 1);
        }
        __syncthreads();
        if (t == 0) g_argw[o] = s_argw;
        int* isrc = H0; int* idst = H1;
        for (int off = 1; off < 256; off <<= 1) {
            __syncthreads();
            int v = isrc[t]; if (t >= off) v += isrc[t - off];
            idst[t] = v;
            int* tmp = isrc; isrc = idst; idst = tmp;
        }
        __syncthreads();
        int excl = (t == 0) ? 0 : isrc[t - 1];
        g_wbs[o * 260 + t] = excl;
        if (t == 255) g_wbs[o * 260 + 256] = D_;
        idst[t] = excl;
        P0[t] = 0.0;
        __syncthreads();
        for (int e = t; e < D_; e += 256) {
            float a = 1.0f - F0[e];
            int k = KY[e];
            int pos = atomicAdd(&idst[k], 1);
            g_wval[o * D_ + pos] = a;
            atomicAdd(&P0[k], (double)a);
        }
        double* dsrc = P0; double* ddst = P1;
        for (int off = 1; off < 256; off <<= 1) {
            __syncthreads();
            double v = dsrc[t]; if (t >= off) v += dsrc[t - off];
            ddst[t] = v;
            double* tmp = dsrc; dsrc = ddst; ddst = tmp;
        }
        __syncthreads();
        g_wbp[o * 256 + t] = dsrc[t];
    } else if (blk < 1536) {
        // ---- transpose x -> g_xT ----
        float (*tile)[33] = (float(*)[33])raw;
        const int tix = blk - 1024;
        const int d0i = (tix & 15) * 32, b0i = (tix >> 4) * 32;
        const int col = t & 31, rr = t >> 5;
#pragma unroll
        for (int i = 0; i < 4; i++) {
            int row = rr + 8 * i;
            tile[row][col] = x[(b0i + row) * D_ + d0i + col];
        }
        __syncthreads();
#pragma unroll
        for (int i = 0; i < 4; i++) {
            int row = rr + 8 * i;
            g_xT[(d0i + row) * B_ + b0i + col] = tile[col][row];
        }
    } else {
        // ---- transpose t -> g_tT ----
        float (*tile)[33] = (float(*)[33])raw;
        const int tix = blk - 1536;
        const int o0i = (tix & 7) * 32, b0i = (tix >> 3) * 32;
        const int col = t & 31, rr = t >> 5;
#pragma unroll
        for (int i = 0; i < 4; i++) {
            int row = rr + 8 * i;
            tile[row][col] = tt[(b0i + row) * O_ + o0i + col];
        }
        __syncthreads();
#pragma unroll
        for (int i = 0; i < 4; i++) {
            int row = rr + 8 * i;
            g_tT[(o0i + row) * B_ + b0i + col] = tile[col][row];
        }
    }
}

// ============================================================
// kB: [0,512) rel_x combine (IDENTICAL) | [512,768) rel_w: 1 block per o, all b
// ============================================================
__global__ __launch_bounds__(256) void kB() {
    __shared__ __align__(16) unsigned char raw[8192];
    const int blk = blockIdx.x;
    const int t = threadIdx.x;

    if (blk < 512) {
        int idx = blk * 256 + t;
        int d = idx >> 8;
        float s = 0.0f;
#pragma unroll
        for (int z = 0; z < NSPLIT; z++) s += g_Mpart[z * (D_ * O_) + idx];
        g_relx[idx] = 1.0f - __fdiv_rn(s, g_Sx[d]);
    } else {
        const int o = blk - 512;
        float*  SV = (float*)raw;            // 512
        int*    BS = (int*)(raw + 2048);     // 257
        double* BP = (double*)(raw + 4096);  // 256
        SV[t] = g_wval[o * D_ + t];
        SV[t + 256] = g_wval[o * D_ + t + 256];
        BS[t] = g_wbs[o * 260 + t];
        if (t == 0) BS[256] = g_wbs[o * 260 + 256];
        BP[t] = g_wbp[o * 256 + t];
        __syncthreads();
        const float sw = (float)BP[255];
#pragma unroll
        for (int ch = 0; ch < 4; ++ch) {
            const int b = ch * 256 + t;
            float c = 1.0f - g_tT[o * B_ + b];
            int k = (int)(c * 256.0f); k = max(0, min(255, k));
            int lo = BS[k], hi = BS[k + 1];
            double S = (k > 0) ? BP[k - 1] : 0.0;
            int ngt = D_ - hi;
            for (int e = lo; e < hi; ++e) {
                float v = SV[e];
                if (v <= c) S += (double)v; else ngt++;
            }
            S += (double)c * (double)ngt;
            g_relwT[o * B_ + b] = 1.0f - __fdiv_rn((float)S, sw);
        }
    }
}

// ============================================================
// kC: [0,256)  per-o: build rel_x buckets in smem, then scan ALL 1024 b -> out0
//     [256,512) per-o: k4 smem binary search for all 1024 b -> out1
// ============================================================
__global__ __launch_bounds__(256) void kC(const float* __restrict__ x,
                                          const float* __restrict__ w,
                                          float* __restrict__ out) {
    __shared__ __align__(16) unsigned char raw[16384];
    const int blk = blockIdx.x;
    const int t = threadIdx.x;

    if (blk < O_) {
        const int o = blk;
        float* CV  = (float*)raw;             // 512
        float* SVa = (float*)(raw + 2048);    // 512
        int*   SI  = (int*)(raw + 4096);      // 512
        float* SB  = (float*)(raw + 6144);    // 512
        int*   KY  = (int*)(raw + 8192);      // 512
        int*   H0  = (int*)(raw + 10240);     // 256
        int*   H1  = (int*)(raw + 11264);     // 256
        float* RD  = (float*)(raw + 12288);   // 256
        float* RX  = (float*)(raw + 13312);   // 256

        CV[t] = g_relx[t * O_ + o];
        CV[t + 256] = g_relx[(t + 256) * O_ + o];
        __syncthreads();
        RD[t] = fminf(CV[t], CV[t + 256]);
        RX[t] = fmaxf(CV[t], CV[t + 256]);
        __syncthreads();
        for (int k = 128; k > 0; k >>= 1) {
            if (t < k) { RD[t] = fminf(RD[t], RD[t + k]); RX[t] = fmaxf(RX[t], RX[t + k]); }
            __syncthreads();
        }
        const float mn = RD[0];
        const float range = RX[0] - mn;
        const float inv = (range > 0.0f) ? 255.0f / range : 0.0f;
        H0[t] = 0;
        __syncthreads();
        for (int e = t; e < D_; e += 256) {
            int k = (int)((CV[e] - mn) * inv); k = max(0, min(255, k));
            KY[e] = k;
            atomicAdd(&H0[k], 1);
        }
        int* isrc = H0; int* idst = H1;
        for (int off = 1; off < 256; off <<= 1) {
            __syncthreads();
            int v = isrc[t]; if (t >= off) v += isrc[t - off];
            idst[t] = v;
            int* tmp = isrc; isrc = idst; idst = tmp;
        }
        __syncthreads();
        const int excl = (t == 0) ? 0 : isrc[t - 1];
        const int bcnt = isrc[t] - excl;
        idst[t] = excl;
        __syncthreads();
        for (int e = t; e < D_; e += 256) {
            int pos = atomicAdd(&idst[KY[e]], 1);
            SVa[pos] = CV[e];
            SI[pos] = e;
        }
        __syncthreads();
        {
            const int end = idst[t];
            const int start = end - bcnt;
            float m = CUDART_INF_F;
            for (int p = start; p < end; ++p) m = fminf(m, SVa[p]);
            for (int p = start; p < end; ++p) SB[p] = m;
        }
        __syncthreads();
        // ---- fused scan: 4 b's per thread, chunk-of-8 prefetch, exact exit ----
#pragma unroll
        for (int chb = 0; chb < 4; ++chb) {
            const int b = chb * 256 + t;
            float best = CUDART_INF_F;
            int bestd = 0x7FFFFFFF;
            for (int ch = 0; ch < D_; ch += 8) {
                if (SB[ch] > best) break;         // exact: SB non-decreasing
                float xv[8];
                int dd[8];
#pragma unroll
                for (int i = 0; i < 8; i++) {
                    dd[i] = SI[ch + i];
                    xv[i] = g_xT[dd[i] * B_ + b]; // independent coalesced loads
                }
#pragma unroll
                for (int i = 0; i < 8; i++) {
                    float v = fmaxf(xv[i], SVa[ch + i]);
                    if (v < best || (v == best && dd[i] < bestd)) { best = v; bestd = dd[i]; }
                }
            }
            out[b * O_ + o] = fmaxf(g_xT[bestd * B_ + b], w[bestd * O_ + o]);
        }
    } else {
        // ---- k4: one block per o, all 1024 b, pm column in smem ----
        const int o = blk - O_;
        float* PM = (float*)raw;              // 512
        PM[t] = g_pmT[o * D_ + t];
        PM[t + 256] = g_pmT[o * D_ + t + 256];
        __syncthreads();
        const int aw = g_argw[o];
#pragma unroll
        for (int chb = 0; chb < 4; ++chb) {
            const int b = chb * 256 + t;
            const float c = g_relwT[o * B_ + b];
            int lo = 0, hi = D_;
            while (lo < hi) {                 // first d with pm[d] <= c
                int mid = (lo + hi) >> 1;
                if (PM[mid] <= c) hi = mid; else lo = mid + 1;
            }
            const int dstar = (lo < D_) ? lo : aw;
            out[B_ * O_ + b * O_ + o] = fmaxf(x[b * D_ + dstar], w[dstar * O_ + o]);
        }
    }
}

// ============================================================
extern "C" void kernel_launch(void* const* d_in, const int* in_sizes, int n_in,
                              void* d_out, int out_size) {
    const float* x = (const float*)d_in[0];   // (B, D)
    const float* w = (const float*)d_in[1];   // (D, O)
    const float* t = (const float*)d_in[2];   // (B, O)
    float* out = (float*)d_out;

    kA<<<1792, 256>>>(x, w, t);
    kB<<<768, 256>>>();
    kC<<<512, 256>>>(x, w, out);
}

// round 8
// speedup vs baseline: 1.0787x; 1.0787x over previous
#include <cuda_runtime.h>
#include <math_constants.h>

#define B_ 1024
#define D_ 512
#define O_ 256
#define NSPLIT 8

// ---- scratch (no allocations allowed) ----
__device__ float  g_Mpart[NSPLIT * D_ * O_];
__device__ float  g_relx[D_ * O_];
__device__ float  g_relwT[O_ * B_];          // rel_w transposed [o][b]
__device__ float  g_Sx[D_];
__device__ float  g_pmT[O_ * D_];            // prefix-min of w, transposed [o][d]
__device__ int    g_argw[O_];
__device__ float  g_xT[D_ * B_];             // x transposed [d][b]
__device__ float  g_tT[O_ * B_];             // t transposed [o][b]
__device__ float  g_wval[O_ * D_];           // bucket-ordered a'=1-w per o
__device__ int    g_wbs[O_ * 260];           // bucket starts per o
__device__ double g_wbp[O_ * 256];           // fp64 inclusive prefix of bucket sums

// ============================================================
// kA: [0,512) k1 partials (32x64 tile, 2x4/thread, vectorized smem)
//     [512,1024) Sx | [1024,1280) w-prep | [1280,1792) transpose x
//     [1792,2048) transpose t
// ============================================================
__global__ __launch_bounds__(256) void kA(const float* __restrict__ x,
                                          const float* __restrict__ w,
                                          const float* __restrict__ tt) {
    __shared__ __align__(16) unsigned char raw[16384];
    __shared__ int s_argw;
    const int blk = blockIdx.x;
    const int t = threadIdx.x;

    if (blk < 512) {
        // ---- k1 partials: values & accumulation order IDENTICAL to R2 ----
        float (*xs)[32] = (float(*)[32])raw;            // [bb][dd] 4KB
        float (*ts)[64] = (float(*)[64])(raw + 4096);   // [bb][oo] 8KB
        const int d0 = (blk & 15) * 32;
        const int o0 = ((blk >> 4) & 3) * 64;
        const int bz = blk >> 6;
        const int b0 = bz * (B_ / NSPLIT);
        const int dg = t & 15;
        const int og = t >> 4;
        float acc[2][4];
#pragma unroll
        for (int i = 0; i < 2; i++)
#pragma unroll
            for (int j = 0; j < 4; j++) acc[i][j] = 0.0f;

        for (int bc = 0; bc < B_ / NSPLIT; bc += 32) {
            {   // xs fill: 1024 floats = 256 float4, 1 per thread
                int bb = t >> 3, dd = (t & 7) * 4;
                float4 v = *(const float4*)(x + (b0 + bc + bb) * D_ + d0 + dd);
                float4 r; r.x = 1.0f - v.x; r.y = 1.0f - v.y;
                r.z = 1.0f - v.z; r.w = 1.0f - v.w;
                *(float4*)&xs[bb][dd] = r;
            }
            {   // ts fill: 2048 floats = 512 float4, 2 per thread
#pragma unroll
                for (int h = 0; h < 2; h++) {
                    int i = t + h * 256;
                    int bb = i >> 4, oo = (i & 15) * 4;
                    float4 v = *(const float4*)(tt + (b0 + bc + bb) * O_ + o0 + oo);
                    float4 r; r.x = 1.0f - v.x; r.y = 1.0f - v.y;
                    r.z = 1.0f - v.z; r.w = 1.0f - v.w;
                    *(float4*)&ts[bb][oo] = r;
                }
            }
            __syncthreads();
#pragma unroll 4
            for (int bb = 0; bb < 32; ++bb) {
                float2 xv = *(const float2*)&xs[bb][dg * 2];
                float4 tv = *(const float4*)&ts[bb][og * 4];
                acc[0][0] += fminf(xv.x, tv.x); acc[0][1] += fminf(xv.x, tv.y);
                acc[0][2] += fminf(xv.x, tv.z); acc[0][3] += fminf(xv.x, tv.w);
                acc[1][0] += fminf(xv.y, tv.x); acc[1][1] += fminf(xv.y, tv.y);
                acc[1][2] += fminf(xv.y, tv.z); acc[1][3] += fminf(xv.y, tv.w);
            }
            __syncthreads();
        }
        float* outp = g_Mpart + bz * (D_ * O_);
#pragma unroll
        for (int i = 0; i < 2; i++) {
            float4 r;
            r.x = acc[i][0]; r.y = acc[i][1]; r.z = acc[i][2]; r.w = acc[i][3];
            *(float4*)(outp + (d0 + dg * 2 + i) * O_ + (o0 + og * 4)) = r;
        }
    } else if (blk < 1024) {
        // ---- Sx[d] (identical math to R2) ----
        float* sm = (float*)raw;
        int d = blk - 512;
        float s = 0.0f;
        for (int b = t; b < B_; b += 256) s += (1.0f - x[b * D_ + d]);
        sm[t] = s; __syncthreads();
        for (int k = 128; k > 0; k >>= 1) {
            if (t < k) sm[t] += sm[t + k];
            __syncthreads();
        }
        if (t == 0) g_Sx[d] = sm[0];
    } else if (blk < 1280) {
        // ---- per-o: prefix-min -> pmT, argw, bucket (1-w), fp64 prefix ----
        const int o = blk - 1024;
        float*  F0 = (float*)raw;
        float*  F1 = (float*)(raw + 2048);
        float*  F2 = (float*)(raw + 4096);
        int*    KY = (int*)(raw + 6144);
        int*    H0 = (int*)(raw + 8192);
        int*    H1 = (int*)(raw + 9216);
        double* P0 = (double*)(raw + 10240);
        double* P1 = (double*)(raw + 12288);

        F0[t] = w[t * O_ + o];
        F0[t + 256] = w[(t + 256) * O_ + o];
        if (t == 0) s_argw = 0x7FFFFFFF;
        F1[t] = F0[t]; F1[t + 256] = F0[t + 256];
        {
            float* src = F1; float* dst = F2;
            for (int off = 1; off < D_; off <<= 1) {
                __syncthreads();
                for (int e = t; e < D_; e += 256) {
                    float v = src[e];
                    if (e >= off) v = fminf(v, src[e - off]);
                    dst[e] = v;
                }
                float* tmp = src; src = dst; dst = tmp;
            }
            __syncthreads();
            for (int e = t; e < D_; e += 256) g_pmT[o * D_ + e] = src[e];
            float wmin = src[D_ - 1];
            __syncthreads();
            for (int e = t; e < D_; e += 256)
                if (F0[e] == wmin) atomicMin(&s_argw, e);
        }
        H0[t] = 0;
        __syncthreads();
        for (int e = t; e < D_; e += 256) {
            float a = 1.0f - F0[e];
            int k = (int)(a * 256.0f); k = max(0, min(255, k));
            KY[e] = k;
            atomicAdd(&H0[k], 1);
        }
        __syncthreads();
        if (t == 0) g_argw[o] = s_argw;
        int* isrc = H0; int* idst = H1;
        for (int off = 1; off < 256; off <<= 1) {
            __syncthreads();
            int v = isrc[t]; if (t >= off) v += isrc[t - off];
            idst[t] = v;
            int* tmp = isrc; isrc = idst; idst = tmp;
        }
        __syncthreads();
        int excl = (t == 0) ? 0 : isrc[t - 1];
        g_wbs[o * 260 + t] = excl;
        if (t == 255) g_wbs[o * 260 + 256] = D_;
        idst[t] = excl;
        P0[t] = 0.0;
        __syncthreads();
        for (int e = t; e < D_; e += 256) {
            float a = 1.0f - F0[e];
            int k = KY[e];
            int pos = atomicAdd(&idst[k], 1);
            g_wval[o * D_ + pos] = a;
            atomicAdd(&P0[k], (double)a);
        }
        double* dsrc = P0; double* ddst = P1;
        for (int off = 1; off < 256; off <<= 1) {
            __syncthreads();
            double v = dsrc[t]; if (t >= off) v += dsrc[t - off];
            ddst[t] = v;
            double* tmp = dsrc; dsrc = ddst; ddst = tmp;
        }
        __syncthreads();
        g_wbp[o * 256 + t] = dsrc[t];
    } else if (blk < 1792) {
        // ---- transpose x -> g_xT ----
        float (*tile)[33] = (float(*)[33])raw;
        const int tix = blk - 1280;
        const int d0i = (tix & 15) * 32, b0i = (tix >> 4) * 32;
        const int col = t & 31, rr = t >> 5;
#pragma unroll
        for (int i = 0; i < 4; i++) {
            int row = rr + 8 * i;
            tile[row][col] = x[(b0i + row) * D_ + d0i + col];
        }
        __syncthreads();
#pragma unroll
        for (int i = 0; i < 4; i++) {
            int row = rr + 8 * i;
            g_xT[(d0i + row) * B_ + b0i + col] = tile[col][row];
        }
    } else {
        // ---- transpose t -> g_tT ----
        float (*tile)[33] = (float(*)[33])raw;
        const int tix = blk - 1792;
        const int o0i = (tix & 7) * 32, b0i = (tix >> 3) * 32;
        const int col = t & 31, rr = t >> 5;
#pragma unroll
        for (int i = 0; i < 4; i++) {
            int row = rr + 8 * i;
            tile[row][col] = tt[(b0i + row) * O_ + o0i + col];
        }
        __syncthreads();
#pragma unroll
        for (int i = 0; i < 4; i++) {
            int row = rr + 8 * i;
            g_tT[(o0i + row) * B_ + b0i + col] = tile[col][row];
        }
    }
}

// ============================================================
// kB: [0,512) rel_x combine (IDENTICAL) | [512,768) rel_w: 1 block per o, all b
// ============================================================
__global__ __launch_bounds__(256) void kB() {
    __shared__ __align__(16) unsigned char raw[8192];
    const int blk = blockIdx.x;
    const int t = threadIdx.x;

    if (blk < 512) {
        int idx = blk * 256 + t;
        int d = idx >> 8;
        float s = 0.0f;
#pragma unroll
        for (int z = 0; z < NSPLIT; z++) s += g_Mpart[z * (D_ * O_) + idx];
        g_relx[idx] = 1.0f - __fdiv_rn(s, g_Sx[d]);
    } else {
        const int o = blk - 512;
        float*  SV = (float*)raw;            // 512
        int*    BS = (int*)(raw + 2048);     // 257
        double* BP = (double*)(raw + 4096);  // 256
        SV[t] = g_wval[o * D_ + t];
        SV[t + 256] = g_wval[o * D_ + t + 256];
        BS[t] = g_wbs[o * 260 + t];
        if (t == 0) BS[256] = g_wbs[o * 260 + 256];
        BP[t] = g_wbp[o * 256 + t];
        __syncthreads();
        const float sw = (float)BP[255];
#pragma unroll
        for (int ch = 0; ch < 4; ++ch) {
            const int b = ch * 256 + t;
            float c = 1.0f - g_tT[o * B_ + b];
            int k = (int)(c * 256.0f); k = max(0, min(255, k));
            int lo = BS[k], hi = BS[k + 1];
            double S = (k > 0) ? BP[k - 1] : 0.0;
            int ngt = D_ - hi;
            for (int e = lo; e < hi; ++e) {
                float v = SV[e];
                if (v <= c) S += (double)v; else ngt++;
            }
            S += (double)c * (double)ngt;
            g_relwT[o * B_ + b] = 1.0f - __fdiv_rn((float)S, sw);
        }
    }
}

// ============================================================
// kC: [0,256)  per-o: build rel_x buckets in smem, then scan ALL 1024 b -> out0
//     [256,512) per-o: k4 smem binary search for all 1024 b -> out1
// ============================================================
__global__ __launch_bounds__(256) void kC(const float* __restrict__ x,
                                          const float* __restrict__ w,
                                          float* __restrict__ out) {
    __shared__ __align__(16) unsigned char raw[16384];
    const int blk = blockIdx.x;
    const int t = threadIdx.x;

    if (blk < O_) {
        const int o = blk;
        float* CV  = (float*)raw;             // 512
        float* SVa = (float*)(raw + 2048);    // 512
        int*   SI  = (int*)(raw + 4096);      // 512
        float* SB  = (float*)(raw + 6144);    // 512
        int*   KY  = (int*)(raw + 8192);      // 512
        int*   H0  = (int*)(raw + 10240);     // 256
        int*   H1  = (int*)(raw + 11264);     // 256
        float* RD  = (float*)(raw + 12288);   // 256
        float* RX  = (float*)(raw + 13312);   // 256

        CV[t] = g_relx[t * O_ + o];
        CV[t + 256] = g_relx[(t + 256) * O_ + o];
        __syncthreads();
        RD[t] = fminf(CV[t], CV[t + 256]);
        RX[t] = fmaxf(CV[t], CV[t + 256]);
        __syncthreads();
        for (int k = 128; k > 0; k >>= 1) {
            if (t < k) { RD[t] = fminf(RD[t], RD[t + k]); RX[t] = fmaxf(RX[t], RX[t + k]); }
            __syncthreads();
        }
        const float mn = RD[0];
        const float range = RX[0] - mn;
        const float inv = (range > 0.0f) ? 255.0f / range : 0.0f;
        H0[t] = 0;
        __syncthreads();
        for (int e = t; e < D_; e += 256) {
            int k = (int)((CV[e] - mn) * inv); k = max(0, min(255, k));
            KY[e] = k;
            atomicAdd(&H0[k], 1);
        }
        int* isrc = H0; int* idst = H1;
        for (int off = 1; off < 256; off <<= 1) {
            __syncthreads();
            int v = isrc[t]; if (t >= off) v += isrc[t - off];
            idst[t] = v;
            int* tmp = isrc; isrc = idst; idst = tmp;
        }
        __syncthreads();
        const int excl = (t == 0) ? 0 : isrc[t - 1];
        const int bcnt = isrc[t] - excl;
        idst[t] = excl;
        __syncthreads();
        for (int e = t; e < D_; e += 256) {
            int pos = atomicAdd(&idst[KY[e]], 1);
            SVa[pos] = CV[e];
            SI[pos] = e;
        }
        __syncthreads();
        {
            const int end = idst[t];
            const int start = end - bcnt;
            float m = CUDART_INF_F;
            for (int p = start; p < end; ++p) m = fminf(m, SVa[p]);
            for (int p = start; p < end; ++p) SB[p] = m;
        }
        __syncthreads();
        // ---- fused scan: 4 b's per thread, chunk-of-8 prefetch, exact exit ----
#pragma unroll
        for (int chb = 0; chb < 4; ++chb) {
            const int b = chb * 256 + t;
            float best = CUDART_INF_F;
            int bestd = 0x7FFFFFFF;
            for (int ch = 0; ch < D_; ch += 8) {
                if (SB[ch] > best) break;         // exact: SB non-decreasing
                float xv[8];
                int dd[8];
#pragma unroll
                for (int i = 0; i < 8; i++) {
                    dd[i] = SI[ch + i];
                    xv[i] = g_xT[dd[i] * B_ + b]; // independent coalesced loads
                }
#pragma unroll
                for (int i = 0; i < 8; i++) {
                    float v = fmaxf(xv[i], SVa[ch + i]);
                    if (v < best || (v == best && dd[i] < bestd)) { best = v; bestd = dd[i]; }
                }
            }
            out[b * O_ + o] = fmaxf(g_xT[bestd * B_ + b], w[bestd * O_ + o]);
        }
    } else {
        // ---- k4: one block per o, all 1024 b, pm column in smem ----
        const int o = blk - O_;
        float* PM = (float*)raw;              // 512
        PM[t] = g_pmT[o * D_ + t];
        PM[t + 256] = g_pmT[o * D_ + t + 256];
        __syncthreads();
        const int aw = g_argw[o];
#pragma unroll
        for (int chb = 0; chb < 4; ++chb) {
            const int b = chb * 256 + t;
            const float c = g_relwT[o * B_ + b];
            int lo = 0, hi = D_;
            while (lo < hi) {                 // first d with pm[d] <= c
                int mid = (lo + hi) >> 1;
                if (PM[mid] <= c) hi = mid; else lo = mid + 1;
            }
            const int dstar = (lo < D_) ? lo : aw;
            out[B_ * O_ + b * O_ + o] = fmaxf(x[b * D_ + dstar], w[dstar * O_ + o]);
        }
    }
}

// ============================================================
extern "C" void kernel_launch(void* const* d_in, const int* in_sizes, int n_in,
                              void* d_out, int out_size) {
    const float* x = (const float*)d_in[0];   // (B, D)
    const float* w = (const float*)d_in[1];   // (D, O)
    const float* t = (const float*)d_in[2];   // (B, O)
    float* out = (float*)d_out;

    kA<<<2048, 256>>>(x, w, t);
    kB<<<768, 256>>>();
    kC<<<512, 256>>>(x, w, out);
}

// round 9
// speedup vs baseline: 1.0986x; 1.0184x over previous
#include <cuda_runtime.h>
#include <math_constants.h>

#define B_ 1024
#define D_ 512
#define O_ 256
#define NSPLIT 8

// ---- scratch (no allocations allowed) ----
__device__ float  g_Mpart[NSPLIT * D_ * O_];
__device__ float  g_relx[D_ * O_];
__device__ float  g_relwT[O_ * B_];          // rel_w transposed [o][b]
__device__ float  g_SxP[32 * D_];            // Sx partials per 32-b tile
__device__ float  g_pmT[O_ * D_];            // prefix-min of w, transposed [o][d]
__device__ int    g_argw[O_];
__device__ float  g_xT[D_ * B_];             // x transposed [d][b]
__device__ float  g_tT[O_ * B_];             // t transposed [o][b]
__device__ float  g_wval[O_ * D_];           // bucket-ordered a'=1-w per o
__device__ int    g_wbs[O_ * 260];           // bucket starts per o
__device__ double g_wbp[O_ * 256];           // fp64 inclusive prefix of bucket sums

// ============================================================
// kA: [0,512) k1 partials (32x64 tile, 2x4/thread, vectorized smem)
//     [512,768) w-prep | [768,1280) transpose x + Sx partials
//     [1280,1536) transpose t
// ============================================================
__global__ __launch_bounds__(256) void kA(const float* __restrict__ x,
                                          const float* __restrict__ w,
                                          const float* __restrict__ tt) {
    __shared__ __align__(16) unsigned char raw[16384];
    __shared__ int s_argw;
    const int blk = blockIdx.x;
    const int t = threadIdx.x;

    if (blk < 512) {
        // ---- k1 partials: values & accumulation order IDENTICAL to R2 ----
        float (*xs)[32] = (float(*)[32])raw;            // [bb][dd] 4KB
        float (*ts)[64] = (float(*)[64])(raw + 4096);   // [bb][oo] 8KB
        const int d0 = (blk & 15) * 32;
        const int o0 = ((blk >> 4) & 3) * 64;
        const int bz = blk >> 6;
        const int b0 = bz * (B_ / NSPLIT);
        const int dg = t & 15;
        const int og = t >> 4;
        float acc[2][4];
#pragma unroll
        for (int i = 0; i < 2; i++)
#pragma unroll
            for (int j = 0; j < 4; j++) acc[i][j] = 0.0f;

        for (int bc = 0; bc < B_ / NSPLIT; bc += 32) {
            {   // xs fill: 1024 floats = 256 float4, 1 per thread
                int bb = t >> 3, dd = (t & 7) * 4;
                float4 v = *(const float4*)(x + (b0 + bc + bb) * D_ + d0 + dd);
                float4 r; r.x = 1.0f - v.x; r.y = 1.0f - v.y;
                r.z = 1.0f - v.z; r.w = 1.0f - v.w;
                *(float4*)&xs[bb][dd] = r;
            }
            {   // ts fill: 2048 floats = 512 float4, 2 per thread
#pragma unroll
                for (int h = 0; h < 2; h++) {
                    int i = t + h * 256;
                    int bb = i >> 4, oo = (i & 15) * 4;
                    float4 v = *(const float4*)(tt + (b0 + bc + bb) * O_ + o0 + oo);
                    float4 r; r.x = 1.0f - v.x; r.y = 1.0f - v.y;
                    r.z = 1.0f - v.z; r.w = 1.0f - v.w;
                    *(float4*)&ts[bb][oo] = r;
                }
            }
            __syncthreads();
#pragma unroll 4
            for (int bb = 0; bb < 32; ++bb) {
                float2 xv = *(const float2*)&xs[bb][dg * 2];
                float4 tv = *(const float4*)&ts[bb][og * 4];
                acc[0][0] += fminf(xv.x, tv.x); acc[0][1] += fminf(xv.x, tv.y);
                acc[0][2] += fminf(xv.x, tv.z); acc[0][3] += fminf(xv.x, tv.w);
                acc[1][0] += fminf(xv.y, tv.x); acc[1][1] += fminf(xv.y, tv.y);
                acc[1][2] += fminf(xv.y, tv.z); acc[1][3] += fminf(xv.y, tv.w);
            }
            __syncthreads();
        }
        float* outp = g_Mpart + bz * (D_ * O_);
#pragma unroll
        for (int i = 0; i < 2; i++) {
            float4 r;
            r.x = acc[i][0]; r.y = acc[i][1]; r.z = acc[i][2]; r.w = acc[i][3];
            *(float4*)(outp + (d0 + dg * 2 + i) * O_ + (o0 + og * 4)) = r;
        }
    } else if (blk < 768) {
        // ---- per-o: prefix-min -> pmT, argw, bucket (1-w), fp64 prefix ----
        const int o = blk - 512;
        float*  F0 = (float*)raw;
        float*  F1 = (float*)(raw + 2048);
        float*  F2 = (float*)(raw + 4096);
        int*    KY = (int*)(raw + 6144);
        int*    H0 = (int*)(raw + 8192);
        int*    H1 = (int*)(raw + 9216);
        double* P0 = (double*)(raw + 10240);
        double* P1 = (double*)(raw + 12288);

        F0[t] = w[t * O_ + o];
        F0[t + 256] = w[(t + 256) * O_ + o];
        if (t == 0) s_argw = 0x7FFFFFFF;
        F1[t] = F0[t]; F1[t + 256] = F0[t + 256];
        {
            float* src = F1; float* dst = F2;
            for (int off = 1; off < D_; off <<= 1) {
                __syncthreads();
                for (int e = t; e < D_; e += 256) {
                    float v = src[e];
                    if (e >= off) v = fminf(v, src[e - off]);
                    dst[e] = v;
                }
                float* tmp = src; src = dst; dst = tmp;
            }
            __syncthreads();
            for (int e = t; e < D_; e += 256) g_pmT[o * D_ + e] = src[e];
            float wmin = src[D_ - 1];
            __syncthreads();
            for (int e = t; e < D_; e += 256)
                if (F0[e] == wmin) atomicMin(&s_argw, e);
        }
        H0[t] = 0;
        __syncthreads();
        for (int e = t; e < D_; e += 256) {
            float a = 1.0f - F0[e];
            int k = (int)(a * 256.0f); k = max(0, min(255, k));
            KY[e] = k;
            atomicAdd(&H0[k], 1);
        }
        __syncthreads();
        if (t == 0) g_argw[o] = s_argw;
        int* isrc = H0; int* idst = H1;
        for (int off = 1; off < 256; off <<= 1) {
            __syncthreads();
            int v = isrc[t]; if (t >= off) v += isrc[t - off];
            idst[t] = v;
            int* tmp = isrc; isrc = idst; idst = tmp;
        }
        __syncthreads();
        int excl = (t == 0) ? 0 : isrc[t - 1];
        g_wbs[o * 260 + t] = excl;
        if (t == 255) g_wbs[o * 260 + 256] = D_;
        idst[t] = excl;
        P0[t] = 0.0;
        __syncthreads();
        for (int e = t; e < D_; e += 256) {
            float a = 1.0f - F0[e];
            int k = KY[e];
            int pos = atomicAdd(&idst[k], 1);
            g_wval[o * D_ + pos] = a;
            atomicAdd(&P0[k], (double)a);
        }
        double* dsrc = P0; double* ddst = P1;
        for (int off = 1; off < 256; off <<= 1) {
            __syncthreads();
            double v = dsrc[t]; if (t >= off) v += dsrc[t - off];
            ddst[t] = v;
            double* tmp = dsrc; dsrc = ddst; ddst = tmp;
        }
        __syncthreads();
        g_wbp[o * 256 + t] = dsrc[t];
    } else if (blk < 1280) {
        // ---- transpose x -> g_xT, plus deterministic Sx partials ----
        float (*tile)[33] = (float(*)[33])raw;                  // 4224 B
        float (*ps)[32]   = (float(*)[32])(raw + 8192);         // 8x32
        const int tix = blk - 768;
        const int d0i = (tix & 15) * 32, b0i = (tix >> 4) * 32;
        const int btile = tix >> 4;                              // 0..31
        const int col = t & 31, rr = t >> 5;                     // rr 0..7
        float psum = 0.0f;
#pragma unroll
        for (int i = 0; i < 4; i++) {
            int row = rr + 8 * i;
            float v = x[(b0i + row) * D_ + d0i + col];
            tile[row][col] = v;
            psum += (1.0f - v);                 // rows rr, rr+8, rr+16, rr+24
        }
        ps[rr][col] = psum;
        __syncthreads();
#pragma unroll
        for (int i = 0; i < 4; i++) {
            int row = rr + 8 * i;
            g_xT[(d0i + row) * B_ + b0i + col] = tile[col][row];
        }
        if (t < 32) {                           // fixed order: rr = 0..7
            float s = 0.0f;
#pragma unroll
            for (int r = 0; r < 8; r++) s += ps[r][t];
            g_SxP[btile * D_ + d0i + t] = s;
        }
    } else {
        // ---- transpose t -> g_tT ----
        float (*tile)[33] = (float(*)[33])raw;
        const int tix = blk - 1280;
        const int o0i = (tix & 7) * 32, b0i = (tix >> 3) * 32;
        const int col = t & 31, rr = t >> 5;
#pragma unroll
        for (int i = 0; i < 4; i++) {
            int row = rr + 8 * i;
            tile[row][col] = tt[(b0i + row) * O_ + o0i + col];
        }
        __syncthreads();
#pragma unroll
        for (int i = 0; i < 4; i++) {
            int row = rr + 8 * i;
            g_tT[(o0i + row) * B_ + b0i + col] = tile[col][row];
        }
    }
}

// ============================================================
// kB: [0,128) rel_x combine, float4 (per-element z-order IDENTICAL)
//     [128,384) rel_w: 1 block per o, all b
// ============================================================
__global__ __launch_bounds__(256) void kB() {
    __shared__ __align__(16) unsigned char raw[8192];
    const int blk = blockIdx.x;
    const int t = threadIdx.x;

    if (blk < 128) {
        __shared__ float sx4[4];
        const int d_base = blk * 4;             // block covers 4 d's (1024 idx)
        if (t < 4) {                            // fixed z order 0..31
            float s = 0.0f;
#pragma unroll
            for (int z = 0; z < 32; z++) s += g_SxP[z * D_ + d_base + t];
            sx4[t] = s;
        }
        __syncthreads();
        const int idx4 = blk * 1024 + t * 4;
        const float sx = sx4[t >> 6];           // d = d_base + (t>>6)
        float4 s = make_float4(0.f, 0.f, 0.f, 0.f);
#pragma unroll
        for (int z = 0; z < NSPLIT; z++) {      // componentwise: same order as R8
            float4 p = *(const float4*)(g_Mpart + z * (D_ * O_) + idx4);
            s.x += p.x; s.y += p.y; s.z += p.z; s.w += p.w;
        }
        float4 r;
        r.x = 1.0f - __fdiv_rn(s.x, sx);
        r.y = 1.0f - __fdiv_rn(s.y, sx);
        r.z = 1.0f - __fdiv_rn(s.z, sx);
        r.w = 1.0f - __fdiv_rn(s.w, sx);
        *(float4*)(g_relx + idx4) = r;
    } else {
        const int o = blk - 128;
        float*  SV = (float*)raw;            // 512
        int*    BS = (int*)(raw + 2048);     // 257
        double* BP = (double*)(raw + 4096);  // 256
        SV[t] = g_wval[o * D_ + t];
        SV[t + 256] = g_wval[o * D_ + t + 256];
        BS[t] = g_wbs[o * 260 + t];
        if (t == 0) BS[256] = g_wbs[o * 260 + 256];
        BP[t] = g_wbp[o * 256 + t];
        __syncthreads();
        const float sw = (float)BP[255];
#pragma unroll
        for (int ch = 0; ch < 4; ++ch) {
            const int b = ch * 256 + t;
            float c = 1.0f - g_tT[o * B_ + b];
            int k = (int)(c * 256.0f); k = max(0, min(255, k));
            int lo = BS[k], hi = BS[k + 1];
            double S = (k > 0) ? BP[k - 1] : 0.0;
            int ngt = D_ - hi;
            for (int e = lo; e < hi; ++e) {
                float v = SV[e];
                if (v <= c) S += (double)v; else ngt++;
            }
            S += (double)c * (double)ngt;
            g_relwT[o * B_ + b] = 1.0f - __fdiv_rn((float)S, sw);
        }
    }
}

// ============================================================
// kC: [0,256)  per-o: build rel_x buckets in smem, then scan ALL 1024 b -> out0
//     [256,512) per-o: k4 smem binary search for all 1024 b -> out1
// ============================================================
__global__ __launch_bounds__(256) void kC(const float* __restrict__ x,
                                          const float* __restrict__ w,
                                          float* __restrict__ out) {
    __shared__ __align__(16) unsigned char raw[16384];
    const int blk = blockIdx.x;
    const int t = threadIdx.x;

    if (blk < O_) {
        const int o = blk;
        float* CV  = (float*)raw;             // 512
        float* SVa = (float*)(raw + 2048);    // 512
        int*   SI  = (int*)(raw + 4096);      // 512
        float* SB  = (float*)(raw + 6144);    // 512
        int*   KY  = (int*)(raw + 8192);      // 512
        int*   H0  = (int*)(raw + 10240);     // 256
        int*   H1  = (int*)(raw + 11264);     // 256
        float* RD  = (float*)(raw + 12288);   // 256
        float* RX  = (float*)(raw + 13312);   // 256

        CV[t] = g_relx[t * O_ + o];
        CV[t + 256] = g_relx[(t + 256) * O_ + o];
        __syncthreads();
        RD[t] = fminf(CV[t], CV[t + 256]);
        RX[t] = fmaxf(CV[t], CV[t + 256]);
        __syncthreads();
        for (int k = 128; k > 0; k >>= 1) {
            if (t < k) { RD[t] = fminf(RD[t], RD[t + k]); RX[t] = fmaxf(RX[t], RX[t + k]); }
            __syncthreads();
        }
        const float mn = RD[0];
        const float range = RX[0] - mn;
        const float inv = (range > 0.0f) ? 255.0f / range : 0.0f;
        H0[t] = 0;
        __syncthreads();
        for (int e = t; e < D_; e += 256) {
            int k = (int)((CV[e] - mn) * inv); k = max(0, min(255, k));
            KY[e] = k;
            atomicAdd(&H0[k], 1);
        }
        int* isrc = H0; int* idst = H1;
        for (int off = 1; off < 256; off <<= 1) {
            __syncthreads();
            int v = isrc[t]; if (t >= off) v += isrc[t - off];
            idst[t] = v;
            int* tmp = isrc; isrc = idst; idst = tmp;
        }
        __syncthreads();
        const int excl = (t == 0) ? 0 : isrc[t - 1];
        const int bcnt = isrc[t] - excl;
        idst[t] = excl;
        __syncthreads();
        for (int e = t; e < D_; e += 256) {
            int pos = atomicAdd(&idst[KY[e]], 1);
            SVa[pos] = CV[e];
            SI[pos] = e;
        }
        __syncthreads();
        {
            const int end = idst[t];
            const int start = end - bcnt;
            float m = CUDART_INF_F;
            for (int p = start; p < end; ++p) m = fminf(m, SVa[p]);
            for (int p = start; p < end; ++p) SB[p] = m;
        }
        __syncthreads();
        // ---- fused scan: 4 b's per thread, chunk-of-8 prefetch, exact exit ----
#pragma unroll
        for (int chb = 0; chb < 4; ++chb) {
            const int b = chb * 256 + t;
            float best = CUDART_INF_F;
            int bestd = 0x7FFFFFFF;
            for (int ch = 0; ch < D_; ch += 8) {
                if (SB[ch] > best) break;         // exact: SB non-decreasing
                float xv[8];
                int dd[8];
#pragma unroll
                for (int i = 0; i < 8; i++) {
                    dd[i] = SI[ch + i];
                    xv[i] = g_xT[dd[i] * B_ + b]; // independent coalesced loads
                }
#pragma unroll
                for (int i = 0; i < 8; i++) {
                    float v = fmaxf(xv[i], SVa[ch + i]);
                    if (v < best || (v == best && dd[i] < bestd)) { best = v; bestd = dd[i]; }
                }
            }
            out[b * O_ + o] = fmaxf(g_xT[bestd * B_ + b], w[bestd * O_ + o]);
        }
    } else {
        // ---- k4: one block per o, all 1024 b, pm column in smem ----
        const int o = blk - O_;
        float* PM = (float*)raw;              // 512
        PM[t] = g_pmT[o * D_ + t];
        PM[t + 256] = g_pmT[o * D_ + t + 256];
        __syncthreads();
        const int aw = g_argw[o];
#pragma unroll
        for (int chb = 0; chb < 4; ++chb) {
            const int b = chb * 256 + t;
            const float c = g_relwT[o * B_ + b];
            int lo = 0, hi = D_;
            while (lo < hi) {                 // first d with pm[d] <= c
                int mid = (lo + hi) >> 1;
                if (PM[mid] <= c) hi = mid; else lo = mid + 1;
            }
            const int dstar = (lo < D_) ? lo : aw;
            out[B_ * O_ + b * O_ + o] = fmaxf(x[b * D_ + dstar], w[dstar * O_ + o]);
        }
    }
}

// ============================================================
extern "C" void kernel_launch(void* const* d_in, const int* in_sizes, int n_in,
                              void* d_out, int out_size) {
    const float* x = (const float*)d_in[0];   // (B, D)
    const float* w = (const float*)d_in[1];   // (D, O)
    const float* t = (const float*)d_in[2];   // (B, O)
    float* out = (float*)d_out;

    kA<<<1536, 256>>>(x, w, t);
    kB<<<384, 256>>>();
    kC<<<512, 256>>>(x, w, out);
}

// round 10
// speedup vs baseline: 1.1217x; 1.0210x over previous
#include <cuda_runtime.h>
#include <math_constants.h>

#define B_ 1024
#define D_ 512
#define O_ 256
#define NSPLIT 16

// ---- scratch (no allocations allowed) ----
__device__ float  g_Mpart[NSPLIT * D_ * O_];   // 8 MB
__device__ float  g_relx[D_ * O_];
__device__ float  g_relwT[O_ * B_];          // rel_w transposed [o][b]
__device__ float  g_SxP[32 * D_];            // Sx partials per 32-b tile
__device__ float  g_pmT[O_ * D_];            // prefix-min of w, transposed [o][d]
__device__ int    g_argw[O_];
__device__ float  g_xT[D_ * B_];             // x transposed [d][b]
__device__ float  g_tT[O_ * B_];             // t transposed [o][b]
__device__ float  g_wval[O_ * D_];           // bucket-ordered a'=1-w per o
__device__ int    g_wbs[O_ * 260];           // bucket starts per o
__device__ double g_wbp[O_ * 256];           // fp64 inclusive prefix of bucket sums

// ============================================================
// kA: [0,512) k1 partials (32d x 128o tile, 4x4/thread, NSPLIT=16)
//     [512,768) w-prep | [768,1280) transpose x + Sx partials
//     [1280,1536) transpose t
// ============================================================
__global__ __launch_bounds__(256) void kA(const float* __restrict__ x,
                                          const float* __restrict__ w,
                                          const float* __restrict__ tt) {
    __shared__ __align__(16) unsigned char raw[20608];
    __shared__ int s_argw;
    const int blk = blockIdx.x;
    const int t = threadIdx.x;

    if (blk < 512) {
        // ---- k1 partials: overall per-cell b-sum remains sequential 0..1023,
        //      bit-identical to the NSPLIT=8 version ----
        float (*xs)[32]  = (float(*)[32])raw;             // [bb][dd] 4KB
        float (*ts)[128] = (float(*)[128])(raw + 4096);   // [bb][oo] 16KB
        const int d0 = (blk & 15) * 32;
        const int o0 = ((blk >> 4) & 1) * 128;
        const int bz = blk >> 5;                // 0..15
        const int b0 = bz * (B_ / NSPLIT);      // 64 b's per split
        const int dg = t & 7;                   // 8 d-groups x 4
        const int og = t >> 3;                  // 32 o-groups x 4
        float acc[4][4];
#pragma unroll
        for (int i = 0; i < 4; i++)
#pragma unroll
            for (int j = 0; j < 4; j++) acc[i][j] = 0.0f;

        for (int bc = 0; bc < B_ / NSPLIT; bc += 32) {
            {   // xs fill: 1024 floats = 256 float4, 1 per thread
                int bb = t >> 3, dd = (t & 7) * 4;
                float4 v = *(const float4*)(x + (b0 + bc + bb) * D_ + d0 + dd);
                float4 r; r.x = 1.0f - v.x; r.y = 1.0f - v.y;
                r.z = 1.0f - v.z; r.w = 1.0f - v.w;
                *(float4*)&xs[bb][dd] = r;
            }
            {   // ts fill: 4096 floats = 1024 float4, 4 per thread
#pragma unroll
                for (int h = 0; h < 4; h++) {
                    int i = t + h * 256;
                    int bb = i >> 5, oo = (i & 31) * 4;
                    float4 v = *(const float4*)(tt + (b0 + bc + bb) * O_ + o0 + oo);
                    float4 r; r.x = 1.0f - v.x; r.y = 1.0f - v.y;
                    r.z = 1.0f - v.z; r.w = 1.0f - v.w;
                    *(float4*)&ts[bb][oo] = r;
                }
            }
            __syncthreads();
#pragma unroll 4
            for (int bb = 0; bb < 32; ++bb) {
                float4 xv = *(const float4*)&xs[bb][dg * 4];
                float4 tv = *(const float4*)&ts[bb][og * 4];
                acc[0][0] += fminf(xv.x, tv.x); acc[0][1] += fminf(xv.x, tv.y);
                acc[0][2] += fminf(xv.x, tv.z); acc[0][3] += fminf(xv.x, tv.w);
                acc[1][0] += fminf(xv.y, tv.x); acc[1][1] += fminf(xv.y, tv.y);
                acc[1][2] += fminf(xv.y, tv.z); acc[1][3] += fminf(xv.y, tv.w);
                acc[2][0] += fminf(xv.z, tv.x); acc[2][1] += fminf(xv.z, tv.y);
                acc[2][2] += fminf(xv.z, tv.z); acc[2][3] += fminf(xv.z, tv.w);
                acc[3][0] += fminf(xv.w, tv.x); acc[3][1] += fminf(xv.w, tv.y);
                acc[3][2] += fminf(xv.w, tv.z); acc[3][3] += fminf(xv.w, tv.w);
            }
            __syncthreads();
        }
        float* outp = g_Mpart + bz * (D_ * O_);
#pragma unroll
        for (int i = 0; i < 4; i++) {
            float4 r;
            r.x = acc[i][0]; r.y = acc[i][1]; r.z = acc[i][2]; r.w = acc[i][3];
            *(float4*)(outp + (d0 + dg * 4 + i) * O_ + (o0 + og * 4)) = r;
        }
    } else if (blk < 768) {
        // ---- per-o: prefix-min -> pmT, argw, bucket (1-w), fp64 prefix ----
        const int o = blk - 512;
        float*  F0 = (float*)raw;
        float*  F1 = (float*)(raw + 2048);
        float*  F2 = (float*)(raw + 4096);
        int*    KY = (int*)(raw + 6144);
        int*    H0 = (int*)(raw + 8192);
        int*    H1 = (int*)(raw + 9216);
        double* P0 = (double*)(raw + 10240);
        double* P1 = (double*)(raw + 12288);

        F0[t] = w[t * O_ + o];
        F0[t + 256] = w[(t + 256) * O_ + o];
        if (t == 0) s_argw = 0x7FFFFFFF;
        F1[t] = F0[t]; F1[t + 256] = F0[t + 256];
        {
            float* src = F1; float* dst = F2;
            for (int off = 1; off < D_; off <<= 1) {
                __syncthreads();
                for (int e = t; e < D_; e += 256) {
                    float v = src[e];
                    if (e >= off) v = fminf(v, src[e - off]);
                    dst[e] = v;
                }
                float* tmp = src; src = dst; dst = tmp;
            }
            __syncthreads();
            for (int e = t; e < D_; e += 256) g_pmT[o * D_ + e] = src[e];
            float wmin = src[D_ - 1];
            __syncthreads();
            for (int e = t; e < D_; e += 256)
                if (F0[e] == wmin) atomicMin(&s_argw, e);
        }
        H0[t] = 0;
        __syncthreads();
        for (int e = t; e < D_; e += 256) {
            float a = 1.0f - F0[e];
            int k = (int)(a * 256.0f); k = max(0, min(255, k));
            KY[e] = k;
            atomicAdd(&H0[k], 1);
        }
        __syncthreads();
        if (t == 0) g_argw[o] = s_argw;
        int* isrc = H0; int* idst = H1;
        for (int off = 1; off < 256; off <<= 1) {
            __syncthreads();
            int v = isrc[t]; if (t >= off) v += isrc[t - off];
            idst[t] = v;
            int* tmp = isrc; isrc = idst; idst = tmp;
        }
        __syncthreads();
        int excl = (t == 0) ? 0 : isrc[t - 1];
        g_wbs[o * 260 + t] = excl;
        if (t == 255) g_wbs[o * 260 + 256] = D_;
        idst[t] = excl;
        P0[t] = 0.0;
        __syncthreads();
        for (int e = t; e < D_; e += 256) {
            float a = 1.0f - F0[e];
            int k = KY[e];
            int pos = atomicAdd(&idst[k], 1);
            g_wval[o * D_ + pos] = a;
            atomicAdd(&P0[k], (double)a);
        }
        double* dsrc = P0; double* ddst = P1;
        for (int off = 1; off < 256; off <<= 1) {
            __syncthreads();
            double v = dsrc[t]; if (t >= off) v += dsrc[t - off];
            ddst[t] = v;
            double* tmp = dsrc; dsrc = ddst; ddst = tmp;
        }
        __syncthreads();
        g_wbp[o * 256 + t] = dsrc[t];
    } else if (blk < 1280) {
        // ---- transpose x -> g_xT, plus deterministic Sx partials ----
        float (*tile)[33] = (float(*)[33])raw;
        float (*ps)[32]   = (float(*)[32])(raw + 8192);
        const int tix = blk - 768;
        const int d0i = (tix & 15) * 32, b0i = (tix >> 4) * 32;
        const int btile = tix >> 4;
        const int col = t & 31, rr = t >> 5;
        float psum = 0.0f;
#pragma unroll
        for (int i = 0; i < 4; i++) {
            int row = rr + 8 * i;
            float v = x[(b0i + row) * D_ + d0i + col];
            tile[row][col] = v;
            psum += (1.0f - v);
        }
        ps[rr][col] = psum;
        __syncthreads();
#pragma unroll
        for (int i = 0; i < 4; i++) {
            int row = rr + 8 * i;
            g_xT[(d0i + row) * B_ + b0i + col] = tile[col][row];
        }
        if (t < 32) {
            float s = 0.0f;
#pragma unroll
            for (int r = 0; r < 8; r++) s += ps[r][t];
            g_SxP[btile * D_ + d0i + t] = s;
        }
    } else {
        // ---- transpose t -> g_tT ----
        float (*tile)[33] = (float(*)[33])raw;
        const int tix = blk - 1280;
        const int o0i = (tix & 7) * 32, b0i = (tix >> 3) * 32;
        const int col = t & 31, rr = t >> 5;
#pragma unroll
        for (int i = 0; i < 4; i++) {
            int row = rr + 8 * i;
            tile[row][col] = tt[(b0i + row) * O_ + o0i + col];
        }
        __syncthreads();
#pragma unroll
        for (int i = 0; i < 4; i++) {
            int row = rr + 8 * i;
            g_tT[(o0i + row) * B_ + b0i + col] = tile[col][row];
        }
    }
}

// ============================================================
// kB: [0,128) rel_x combine, float4 (overall b-sum bit-identical)
//     [128,384) rel_w: 1 block per o, all b
// ============================================================
__global__ __launch_bounds__(256) void kB() {
    __shared__ __align__(16) unsigned char raw[8192];
    const int blk = blockIdx.x;
    const int t = threadIdx.x;

    if (blk < 128) {
        __shared__ float sx4[4];
        const int d_base = blk * 4;
        if (t < 4) {
            float s = 0.0f;
#pragma unroll
            for (int z = 0; z < 32; z++) s += g_SxP[z * D_ + d_base + t];
            sx4[t] = s;
        }
        __syncthreads();
        const int idx4 = blk * 1024 + t * 4;
        const float sx = sx4[t >> 6];
        float4 s = make_float4(0.f, 0.f, 0.f, 0.f);
#pragma unroll
        for (int z = 0; z < NSPLIT; z++) {     // z ascending: sequential b-sum
            float4 p = *(const float4*)(g_Mpart + z * (D_ * O_) + idx4);
            s.x += p.x; s.y += p.y; s.z += p.z; s.w += p.w;
        }
        float4 r;
        r.x = 1.0f - __fdiv_rn(s.x, sx);
        r.y = 1.0f - __fdiv_rn(s.y, sx);
        r.z = 1.0f - __fdiv_rn(s.z, sx);
        r.w = 1.0f - __fdiv_rn(s.w, sx);
        *(float4*)(g_relx + idx4) = r;
    } else {
        const int o = blk - 128;
        float*  SV = (float*)raw;            // 512
        int*    BS = (int*)(raw + 2048);     // 257
        double* BP = (double*)(raw + 4096);  // 256
        SV[t] = g_wval[o * D_ + t];
        SV[t + 256] = g_wval[o * D_ + t + 256];
        BS[t] = g_wbs[o * 260 + t];
        if (t == 0) BS[256] = g_wbs[o * 260 + 256];
        BP[t] = g_wbp[o * 256 + t];
        __syncthreads();
        const float sw = (float)BP[255];
#pragma unroll
        for (int ch = 0; ch < 4; ++ch) {
            const int b = ch * 256 + t;
            float c = 1.0f - g_tT[o * B_ + b];
            int k = (int)(c * 256.0f); k = max(0, min(255, k));
            int lo = BS[k], hi = BS[k + 1];
            double S = (k > 0) ? BP[k - 1] : 0.0;
            int ngt = D_ - hi;
            for (int e = lo; e < hi; ++e) {
                float v = SV[e];
                if (v <= c) S += (double)v; else ngt++;
            }
            S += (double)c * (double)ngt;
            g_relwT[o * B_ + b] = 1.0f - __fdiv_rn((float)S, sw);
        }
    }
}

// ============================================================
// kC: [0,256)  per-o: build rel_x buckets in smem, then scan ALL 1024 b -> out0
//     [256,512) per-o: k4 smem binary search for all 1024 b -> out1
// ============================================================
__global__ __launch_bounds__(256) void kC(const float* __restrict__ x,
                                          const float* __restrict__ w,
                                          float* __restrict__ out) {
    __shared__ __align__(16) unsigned char raw[16384];
    const int blk = blockIdx.x;
    const int t = threadIdx.x;

    if (blk < O_) {
        const int o = blk;
        float* CV  = (float*)raw;             // 512
        float* SVa = (float*)(raw + 2048);    // 512
        int*   SI  = (int*)(raw + 4096);      // 512
        float* SB  = (float*)(raw + 6144);    // 512
        int*   KY  = (int*)(raw + 8192);      // 512
        int*   H0  = (int*)(raw + 10240);     // 256
        int*   H1  = (int*)(raw + 11264);     // 256
        float* RD  = (float*)(raw + 12288);   // 256
        float* RX  = (float*)(raw + 13312);   // 256

        CV[t] = g_relx[t * O_ + o];
        CV[t + 256] = g_relx[(t + 256) * O_ + o];
        __syncthreads();
        RD[t] = fminf(CV[t], CV[t + 256]);
        RX[t] = fmaxf(CV[t], CV[t + 256]);
        __syncthreads();
        for (int k = 128; k > 0; k >>= 1) {
            if (t < k) { RD[t] = fminf(RD[t], RD[t + k]); RX[t] = fmaxf(RX[t], RX[t + k]); }
            __syncthreads();
        }
        const float mn = RD[0];
        const float range = RX[0] - mn;
        const float inv = (range > 0.0f) ? 255.0f / range : 0.0f;
        H0[t] = 0;
        __syncthreads();
        for (int e = t; e < D_; e += 256) {
            int k = (int)((CV[e] - mn) * inv); k = max(0, min(255, k));
            KY[e] = k;
            atomicAdd(&H0[k], 1);
        }
        int* isrc = H0; int* idst = H1;
        for (int off = 1; off < 256; off <<= 1) {
            __syncthreads();
            int v = isrc[t]; if (t >= off) v += isrc[t - off];
            idst[t] = v;
            int* tmp = isrc; isrc = idst; idst = tmp;
        }
        __syncthreads();
        const int excl = (t == 0) ? 0 : isrc[t - 1];
        const int bcnt = isrc[t] - excl;
        idst[t] = excl;
        __syncthreads();
        for (int e = t; e < D_; e += 256) {
            int pos = atomicAdd(&idst[KY[e]], 1);
            SVa[pos] = CV[e];
            SI[pos] = e;
        }
        __syncthreads();
        {
            const int end = idst[t];
            const int start = end - bcnt;
            float m = CUDART_INF_F;
            for (int p = start; p < end; ++p) m = fminf(m, SVa[p]);
            for (int p = start; p < end; ++p) SB[p] = m;
        }
        __syncthreads();
        // ---- fused scan: 4 b's per thread, chunk-of-8 prefetch, exact exit ----
#pragma unroll
        for (int chb = 0; chb < 4; ++chb) {
            const int b = chb * 256 + t;
            float best = CUDART_INF_F;
            int bestd = 0x7FFFFFFF;
            for (int ch = 0; ch < D_; ch += 8) {
                if (SB[ch] > best) break;         // exact: SB non-decreasing
                float xv[8];
                int dd[8];
#pragma unroll
                for (int i = 0; i < 8; i++) {
                    dd[i] = SI[ch + i];
                    xv[i] = g_xT[dd[i] * B_ + b]; // independent coalesced loads
                }
#pragma unroll
                for (int i = 0; i < 8; i++) {
                    float v = fmaxf(xv[i], SVa[ch + i]);
                    if (v < best || (v == best && dd[i] < bestd)) { best = v; bestd = dd[i]; }
                }
            }
            out[b * O_ + o] = fmaxf(g_xT[bestd * B_ + b], w[bestd * O_ + o]);
        }
    } else {
        // ---- k4: one block per o, all 1024 b, pm column in smem ----
        const int o = blk - O_;
        float* PM = (float*)raw;              // 512
        PM[t] = g_pmT[o * D_ + t];
        PM[t + 256] = g_pmT[o * D_ + t + 256];
        __syncthreads();
        const int aw = g_argw[o];
#pragma unroll
        for (int chb = 0; chb < 4; ++chb) {
            const int b = chb * 256 + t;
            const float c = g_relwT[o * B_ + b];
            int lo = 0, hi = D_;
            while (lo < hi) {                 // first d with pm[d] <= c
                int mid = (lo + hi) >> 1;
                if (PM[mid] <= c) hi = mid; else lo = mid + 1;
            }
            const int dstar = (lo < D_) ? lo : aw;
            out[B_ * O_ + b * O_ + o] = fmaxf(x[b * D_ + dstar], w[dstar * O_ + o]);
        }
    }
}

// ============================================================
extern "C" void kernel_launch(void* const* d_in, const int* in_sizes, int n_in,
                              void* d_out, int out_size) {
    const float* x = (const float*)d_in[0];   // (B, D)
    const float* w = (const float*)d_in[1];   // (D, O)
    const float* t = (const float*)d_in[2];   // (B, O)
    float* out = (float*)d_out;

    kA<<<1536, 256>>>(x, w, t);
    kB<<<384, 256>>>();
    kC<<<512, 256>>>(x, w, out);
}